// round 4
// baseline (speedup 1.0000x reference)
#include <cuda_runtime.h>

#define NUM_LABELS 51
#define CH 16
#define SPATIAL (32 * 256 * 256)   // 2097152 = 1<<21
#define NVOX (2 * SPATIAL)         // 4194304
#define PAD 17
#define EPSF 1e-8f

// Global scratch (no allocations allowed)
__device__ float g_sum[NUM_LABELS * CH];
__device__ float g_nsum[NUM_LABELS * CH];
__device__ float g_cnt[NUM_LABELS];

__global__ void k_zero() {
    int i = threadIdx.x;
    if (i < NUM_LABELS * CH) { g_sum[i] = 0.f; g_nsum[i] = 0.f; }
    if (i < NUM_LABELS) g_cnt[i] = 0.f;
}

__global__ __launch_bounds__(256) void k_main(const float* __restrict__ pred,
                                              const int* __restrict__ gt) {
    __shared__ float s_sum[NUM_LABELS * PAD];
    __shared__ float s_nsum[NUM_LABELS * PAD];
    __shared__ float s_cnt[NUM_LABELS];

    for (int i = threadIdx.x; i < NUM_LABELS * PAD; i += 256) {
        s_sum[i] = 0.f;
        s_nsum[i] = 0.f;
    }
    if (threadIdx.x < NUM_LABELS) s_cnt[threadIdx.x] = 0.f;
    __syncthreads();

    int stride = gridDim.x * 256;
    for (int n = blockIdx.x * 256 + threadIdx.x; n < NVOX; n += stride) {
        int l = gt[n];
        // label 0 contributes nothing downstream; also guard out-of-range
        if ((unsigned)(l - 1) > 49u) continue;

        int b  = n >> 21;               // batch
        int sp = n & (SPATIAL - 1);     // spatial offset within batch
        const float* base = pred + ((long)b << 25) + sp;  // b*16*SPATIAL + sp

        float v[CH];
        float ss = 0.f;
        #pragma unroll
        for (int c = 0; c < CH; c++) {
            v[c] = base[(long)c << 21]; // channel stride = SPATIAL, coalesced per channel
            ss += v[c] * v[c];
        }
        float rinv = rsqrtf(ss);

        float* ps = &s_sum[l * PAD];
        float* pn = &s_nsum[l * PAD];
        #pragma unroll
        for (int c = 0; c < CH; c++) {
            atomicAdd(ps + c, v[c]);
            atomicAdd(pn + c, v[c] * rinv);
        }
        atomicAdd(&s_cnt[l], 1.f);
    }
    __syncthreads();

    // Flush block-private accumulators to global
    for (int i = threadIdx.x; i < NUM_LABELS * CH; i += 256) {
        int l = i >> 4, c = i & 15;
        atomicAdd(&g_sum[i],  s_sum[l * PAD + c]);
        atomicAdd(&g_nsum[i], s_nsum[l * PAD + c]);
    }
    if (threadIdx.x < NUM_LABELS) atomicAdd(&g_cnt[threadIdx.x], s_cnt[threadIdx.x]);
}

__global__ void k_final(float* __restrict__ out) {
    __shared__ float s_m[50 * 16];   // means for labels 1..50
    __shared__ float s_in[50];       // 1/max(|m|, eps)
    __shared__ float s_acc[2];       // [0]=inter sum, [1]=intra sum
    int tid = threadIdx.x;
    if (tid < 2) s_acc[tid] = 0.f;
    __syncthreads();

    // means (labels 1..50)
    for (int i = tid; i < 800; i += blockDim.x) {
        int l = (i >> 4) + 1;
        float c = fmaxf(g_cnt[l], 1.f);
        s_m[i] = g_sum[(l << 4) + (i & 15)] / c;
    }
    __syncthreads();

    // norms + per-label intra contribution:
    // intra_l = dot(m_l, nsum_l) / (|m_l| * count_l)
    for (int l0 = tid; l0 < 50; l0 += blockDim.x) {
        int l = l0 + 1;
        float n2 = 0.f;
        #pragma unroll
        for (int c = 0; c < 16; c++) { float m = s_m[l0 * 16 + c]; n2 += m * m; }
        float nrm = sqrtf(n2);
        s_in[l0] = 1.f / fmaxf(nrm, EPSF);

        float dot = 0.f;
        #pragma unroll
        for (int c = 0; c < 16; c++) dot += s_m[l0 * 16 + c] * g_nsum[(l << 4) + c];
        float cnt = fmaxf(g_cnt[l], 1.f);
        float intra_l = dot / (fmaxf(nrm, 1e-30f) * cnt);
        atomicAdd(&s_acc[1], intra_l);
    }
    __syncthreads();

    // normalize means in place
    for (int i = tid; i < 800; i += blockDim.x) s_m[i] *= s_in[i >> 4];
    __syncthreads();

    // upper-triangular Gram pairs, clipped to [0,1]
    float local = 0.f;
    for (int p = tid; p < 1225; p += blockDim.x) {
        int i = 0, rem = p;
        while (rem >= 49 - i) { rem -= 49 - i; i++; }
        int j = i + 1 + rem;
        float dot = 0.f;
        #pragma unroll
        for (int c = 0; c < 16; c++) dot += s_m[i * 16 + c] * s_m[j * 16 + c];
        local += fminf(fmaxf(dot, 0.f), 1.f);
    }
    atomicAdd(&s_acc[0], local);
    __syncthreads();

    if (tid == 0) out[0] = s_acc[0] * (1.f / 1225.f) - s_acc[1] * (1.f / 50.f);
}

extern "C" void kernel_launch(void* const* d_in, const int* in_sizes, int n_in,
                              void* d_out, int out_size) {
    const float* pred = (const float*)d_in[0];
    const int* gt = (const int*)d_in[1];
    float* out = (float*)d_out;

    k_zero<<<1, 1024>>>();
    k_main<<<1184, 256>>>(pred, gt);
    k_final<<<1, 256>>>(out);
}

// round 5
// speedup vs baseline: 2.0532x; 2.0532x over previous
#include <cuda_runtime.h>

#define NUM_LABELS 51
#define CH 16
#define SPATIAL (32 * 256 * 256)   // 2097152 = 1<<21
#define NVOX (2 * SPATIAL)         // 4194304
#define EPSF 1e-8f

#define V 512        // voxels per tile (NVOX divisible: 8192 tiles)
#define VPT 2        // voxels per thread per tile (256 threads)
#define STRIDE 20    // 16 channels + rinv, padded to multiple of 4 for float4

// Global scratch (no allocations allowed)
__device__ float g_sum[NUM_LABELS * CH];
__device__ float g_nsum[NUM_LABELS * CH];
__device__ float g_cnt[NUM_LABELS];

__global__ void k_zero() {
    int i = threadIdx.x;
    if (i < NUM_LABELS * CH) { g_sum[i] = 0.f; g_nsum[i] = 0.f; }
    if (i < NUM_LABELS) g_cnt[i] = 0.f;
}

__global__ __launch_bounds__(256) void k_main(const float* __restrict__ pred,
                                              const int* __restrict__ gt) {
    __shared__ __align__(16) float s_data[V * STRIDE];  // 40 KB
    __shared__ int s_hist[NUM_LABELS];
    __shared__ int s_base[NUM_LABELS];

    int tid = threadIdx.x;

    // Persistent register accumulators: thread t < 200 owns (label l, channel group g)
    // l = t/4 + 1, channels [4g, 4g+3]
    float4 aS = make_float4(0.f, 0.f, 0.f, 0.f);
    float4 aN = make_float4(0.f, 0.f, 0.f, 0.f);
    int cntAcc = 0;   // thread l (1..50) accumulates count of label l

    const int nTiles = NVOX / V;   // 8192
    for (int tile = blockIdx.x; tile < nTiles; tile += gridDim.x) {
        int n0 = tile * V;

        if (tid < NUM_LABELS) s_hist[tid] = 0;
        __syncthreads();

        // ---- Phase 1: count + rank (1 shared atomic per voxel) ----
        int lab[VPT], rnk[VPT];
        #pragma unroll
        for (int k = 0; k < VPT; k++) {
            int n = n0 + tid + k * 256;
            int l = gt[n];                       // coalesced int32 load
            lab[k] = ((unsigned)(l - 1) <= 49u) ? l : -1;   // drop label 0 / OOR
            rnk[k] = (lab[k] > 0) ? atomicAdd(&s_hist[lab[k]], 1) : 0;
        }
        __syncthreads();

        // ---- Phase 2: exclusive scan over bins (cheap, 51 entries) ----
        if (tid < NUM_LABELS) {
            int b = 0;
            for (int j = 0; j < tid; j++) b += s_hist[j];
            s_base[tid] = b;
            cntAcc += s_hist[tid];               // per-label running count
        }
        __syncthreads();

        // ---- Phase 3: load pred, compute rinv, store label-sorted to shared ----
        #pragma unroll
        for (int k = 0; k < VPT; k++) {
            if (lab[k] < 0) continue;
            int n  = n0 + tid + k * 256;
            int b  = n >> 21;
            int sp = n & (SPATIAL - 1);
            const float* basep = pred + ((long)b << 25) + sp;

            float v[CH];
            float ss = 0.f;
            #pragma unroll
            for (int c = 0; c < CH; c++) {
                v[c] = basep[(long)c << 21];     // coalesced per channel
                ss += v[c] * v[c];
            }
            float rinv = rsqrtf(ss);

            float* d = &s_data[(s_base[lab[k]] + rnk[k]) * STRIDE];  // 16B aligned
            #pragma unroll
            for (int q = 0; q < 4; q++)
                *(float4*)(d + 4 * q) = make_float4(v[4*q], v[4*q+1], v[4*q+2], v[4*q+3]);
            d[16] = rinv;
        }
        __syncthreads();

        // ---- Phase 4: atomic-free segmented reduce into registers ----
        if (tid < 200) {
            int l = (tid >> 2) + 1;
            int g = tid & 3;
            int b0  = s_base[l];
            int cnt = s_hist[l];
            for (int j = 0; j < cnt; j++) {
                const float* e = &s_data[(b0 + j) * STRIDE];
                float4 v4 = *(const float4*)(e + 4 * g);   // LDS.128
                float  ri = e[16];                         // broadcast within 4-lane cluster
                aS.x += v4.x; aS.y += v4.y; aS.z += v4.z; aS.w += v4.w;
                aN.x += v4.x * ri; aN.y += v4.y * ri; aN.z += v4.z * ri; aN.w += v4.w * ri;
            }
        }
        __syncthreads();
    }

    // ---- Flush (once per block) ----
    if (tid < 200) {
        int l = (tid >> 2) + 1;
        int g = tid & 3;
        int o = l * CH + 4 * g;
        atomicAdd(&g_sum[o + 0], aS.x); atomicAdd(&g_sum[o + 1], aS.y);
        atomicAdd(&g_sum[o + 2], aS.z); atomicAdd(&g_sum[o + 3], aS.w);
        atomicAdd(&g_nsum[o + 0], aN.x); atomicAdd(&g_nsum[o + 1], aN.y);
        atomicAdd(&g_nsum[o + 2], aN.z); atomicAdd(&g_nsum[o + 3], aN.w);
    }
    if (tid >= 1 && tid <= 50) atomicAdd(&g_cnt[tid], (float)cntAcc);
}

__global__ void k_final(float* __restrict__ out) {
    __shared__ float s_m[50 * 16];   // means for labels 1..50
    __shared__ float s_in[50];       // 1/max(|m|, eps)
    __shared__ float s_acc[2];       // [0]=inter sum, [1]=intra sum
    int tid = threadIdx.x;
    if (tid < 2) s_acc[tid] = 0.f;
    __syncthreads();

    // means (labels 1..50)
    for (int i = tid; i < 800; i += blockDim.x) {
        int l = (i >> 4) + 1;
        float c = fmaxf(g_cnt[l], 1.f);
        s_m[i] = g_sum[(l << 4) + (i & 15)] / c;
    }
    __syncthreads();

    // norms + per-label intra contribution: intra_l = dot(m_l, nsum_l) / (|m_l| * count_l)
    for (int l0 = tid; l0 < 50; l0 += blockDim.x) {
        int l = l0 + 1;
        float n2 = 0.f;
        #pragma unroll
        for (int c = 0; c < 16; c++) { float m = s_m[l0 * 16 + c]; n2 += m * m; }
        float nrm = sqrtf(n2);
        s_in[l0] = 1.f / fmaxf(nrm, EPSF);

        float dot = 0.f;
        #pragma unroll
        for (int c = 0; c < 16; c++) dot += s_m[l0 * 16 + c] * g_nsum[(l << 4) + c];
        float cnt = fmaxf(g_cnt[l], 1.f);
        float intra_l = dot / (fmaxf(nrm, 1e-30f) * cnt);
        atomicAdd(&s_acc[1], intra_l);
    }
    __syncthreads();

    // normalize means in place
    for (int i = tid; i < 800; i += blockDim.x) s_m[i] *= s_in[i >> 4];
    __syncthreads();

    // upper-triangular Gram pairs, clipped to [0,1]
    float local = 0.f;
    for (int p = tid; p < 1225; p += blockDim.x) {
        int i = 0, rem = p;
        while (rem >= 49 - i) { rem -= 49 - i; i++; }
        int j = i + 1 + rem;
        float dot = 0.f;
        #pragma unroll
        for (int c = 0; c < 16; c++) dot += s_m[i * 16 + c] * s_m[j * 16 + c];
        local += fminf(fmaxf(dot, 0.f), 1.f);
    }
    atomicAdd(&s_acc[0], local);
    __syncthreads();

    if (tid == 0) out[0] = s_acc[0] * (1.f / 1225.f) - s_acc[1] * (1.f / 50.f);
}

extern "C" void kernel_launch(void* const* d_in, const int* in_sizes, int n_in,
                              void* d_out, int out_size) {
    const float* pred = (const float*)d_in[0];
    const int* gt = (const int*)d_in[1];
    float* out = (float*)d_out;

    k_zero<<<1, 1024>>>();
    k_main<<<740, 256>>>(pred, gt);   // 148 SMs x ~5 blocks (40KB smem each)
    k_final<<<1, 256>>>(out);
}